// round 5
// baseline (speedup 1.0000x reference)
#include <cuda_runtime.h>
#include <math.h>

// LatentRNN: B=2048, T=512, P=8, L=64, H=180
// 128 persistent CTAs x 16 batch rows, 768 threads (24 warps).
// Fused GRU (no gi/gh materialization), single-pass phase C with
// double-buffered KT=12 weight tiles, vector LDS.128 weight reads.

#define B_    2048
#define T_    512
#define P_    8
#define L_    64
#define H_    180
#define IN_K  72
#define BT    16
#define NTHR  768

#define C_KT  12
#define C_NT  15           // 180 / 12
#define C_WS  12           // row stride in staged tile (floats); 12j%32 conflict-free
#define B_WS  76           // W_in staged stride (76j%32 = 12j -> distinct)
#define D_WS  68           // W_o1 tile stride (68j%32 = 4j -> distinct)
#define E_WS  188          // W_o2 persistent stride (188j%32 = 28j -> distinct)
#define H0_WS 68

struct __align__(16) Smem {
    float inT [IN_K][BT];      // [phys_t ; cur] transposed
    float xT  [H_][BT];        // gelu(in @ W_in^T)
    float hT  [2][H_][BT];     // hidden state, double buffered
    float oT  [H_][BT];        // gelu(cat @ W_o1^T)
    float cur [BT][L_];        // current latents (row-major)
    float curT[L_][BT];        // current latents (transposed, for D tile 3)
    float WE  [L_ * E_WS];     // persistent staged W_o2
    float bias[1504];          // [0,540) b_ih | [540,1080) b_hh | [1080,1260) b_in
                               // [1260,1440) b_o1 | [1440,1504) b_o2
    float Wt  [2 * 1080 * C_WS]; // staging union (25920 floats): C double-buffer;
                               // B uses 13680 @0; D uses 2 x 180*68; h0 uses 180*68
};

__device__ __forceinline__ float gelu_f(float v) {
    return 0.5f * v * (1.0f + erff(v * 0.70710678118654752440f));
}
__device__ __forceinline__ float sigmoid_f(float v) {
    return 1.0f / (1.0f + expf(-v));
}

// acc[r] += sum over 4 k of act_k[r] * w[k]   (a0..a3 = act rows k..k+3)
__device__ __forceinline__ void fma16(float* __restrict__ acc,
                                      const float4 a0, const float4 a1,
                                      const float4 a2, const float4 a3,
                                      const float4 w) {
    acc[0] = fmaf(a0.x, w.x, acc[0]); acc[0] = fmaf(a1.x, w.y, acc[0]);
    acc[0] = fmaf(a2.x, w.z, acc[0]); acc[0] = fmaf(a3.x, w.w, acc[0]);
    acc[1] = fmaf(a0.y, w.x, acc[1]); acc[1] = fmaf(a1.y, w.y, acc[1]);
    acc[1] = fmaf(a2.y, w.z, acc[1]); acc[1] = fmaf(a3.y, w.w, acc[1]);
    acc[2] = fmaf(a0.z, w.x, acc[2]); acc[2] = fmaf(a1.z, w.y, acc[2]);
    acc[2] = fmaf(a2.z, w.z, acc[2]); acc[2] = fmaf(a3.z, w.w, acc[2]);
    acc[3] = fmaf(a0.w, w.x, acc[3]); acc[3] = fmaf(a1.w, w.y, acc[3]);
    acc[3] = fmaf(a2.w, w.z, acc[3]); acc[3] = fmaf(a3.w, w.w, acc[3]);
}

// ---- staging helpers ----

// Phase C tile: 1080 virtual rows (W_ih 0..539 | W_hh 540..1079) x 12 k.
// dst word offset == 4*i identically (r*12 + 4c with i = 3r + c).
__device__ __forceinline__ void stageC(float* __restrict__ dst,
                                       const float* __restrict__ Wih,
                                       const float* __restrict__ Whh,
                                       int k0, int tid) {
    for (int i = tid; i < 3240; i += NTHR) {
        int r = i / 3;
        int c = i - r * 3;
        const float* src = (r < 540) ? (Wih + r * H_ + k0 + c * 4)
                                     : (Whh + (r - 540) * H_ + k0 + c * 4);
        *(float4*)(dst + 4 * i) = *(const float4*)src;
    }
}

// Simple column phase (used by B and h0): out[j][ro..ro+3] from K-deep GEMM.
template<int K, int WSP, bool GELU>
__device__ __forceinline__ void simple_phase(const float* __restrict__ wt,
                                             const float* __restrict__ bias,
                                             const float (*__restrict__ act)[BT],
                                             float (*__restrict__ outT)[BT],
                                             int tid) {
    const int j = tid >> 2, q = tid & 3, ro = q * 4;
    if (j < H_) {
        float acc[4] = {0.f, 0.f, 0.f, 0.f};
        const float* wp = wt + j * WSP;
#pragma unroll
        for (int k = 0; k < K; k += 4) {
            float4 w4 = *(const float4*)(wp + k);
            float4 a0 = *(const float4*)&act[k + 0][ro];
            float4 a1 = *(const float4*)&act[k + 1][ro];
            float4 a2 = *(const float4*)&act[k + 2][ro];
            float4 a3 = *(const float4*)&act[k + 3][ro];
            fma16(acc, a0, a1, a2, a3, w4);
        }
        float bb = bias[j];
        float4 f;
        f.x = acc[0] + bb; f.y = acc[1] + bb; f.z = acc[2] + bb; f.w = acc[3] + bb;
        if (GELU) { f.x = gelu_f(f.x); f.y = gelu_f(f.y);
                    f.z = gelu_f(f.z); f.w = gelu_f(f.w); }
        *(float4*)&outT[j][ro] = f;
    }
}

__global__ __launch_bounds__(NTHR, 1)
void latent_rnn_kernel(const float* __restrict__ phys,
                       const float* __restrict__ latents,
                       const float* __restrict__ W_in, const float* __restrict__ b_in,
                       const float* __restrict__ W_hp, const float* __restrict__ b_hp,
                       const float* __restrict__ W_ih, const float* __restrict__ b_ih,
                       const float* __restrict__ W_hh, const float* __restrict__ b_hh,
                       const float* __restrict__ W_o1, const float* __restrict__ b_o1,
                       const float* __restrict__ W_o2, const float* __restrict__ b_o2,
                       float* __restrict__ out)
{
    extern __shared__ char smem_raw[];
    Smem* s = reinterpret_cast<Smem*>(smem_raw);
    const int tid = threadIdx.x;
    const int b0  = blockIdx.x * BT;
    const int j   = tid >> 2;        // column task id (0..191, active < 180)
    const int q   = tid & 3;
    const int ro  = q * 4;
    const bool on = (j < H_);

    // ---- one-time init ----
    // cur / curT = latents
    for (int i = tid; i < BT * L_; i += NTHR) {
        int r = i >> 6, l = i & 63;
        float v = latents[(b0 + r) * L_ + l];
        s->cur[r][l]  = v;
        s->curT[l][r] = v;
    }
    // biases into smem
    for (int i = tid; i < 540; i += NTHR) s->bias[i]        = b_ih[i];
    for (int i = tid; i < 540; i += NTHR) s->bias[540 + i]  = b_hh[i];
    for (int i = tid; i < 180; i += NTHR) s->bias[1080 + i] = b_in[i];
    for (int i = tid; i < 180; i += NTHR) s->bias[1260 + i] = b_o1[i];
    for (int i = tid; i < 64;  i += NTHR) s->bias[1440 + i] = b_o2[i];
    // persistent W_o2 -> WE (64 rows x 45 float4, stride E_WS)
    for (int i = tid; i < 64 * 45; i += NTHR) {
        int r = i / 45, c = i - r * 45;
        *(float4*)(s->WE + r * E_WS + c * 4) = *(const float4*)(W_o2 + r * H_ + c * 4);
    }
    // stage W_hp (180 x 64, stride H0_WS) into Wt
    for (int i = tid; i < 180 * 16; i += NTHR) {
        int r = i >> 4, c = i & 15;
        *(float4*)(s->Wt + r * H0_WS + c * 4) = *(const float4*)(W_hp + r * L_ + c * 4);
    }
    __syncthreads();

    // h0 = latents @ W_hp^T + b_hp  (act = curT, K = 64)
    simple_phase<L_, H0_WS, false>(s->Wt, s->bias + 1080 /*unused-safe*/, 
                                   (const float (*)[BT])s->curT, s->hT[0], tid);
    // NOTE: bias for h0 is b_hp (all zeros per setup, but stay faithful):
    if (on) {   // overwrite with correct bias applied (b_hp)
        float4 f = *(float4*)&s->hT[0][j][ro];
        float bb = b_hp[j] - s->bias[1080 + j];   // remove b_in, add b_hp
        f.x += bb; f.y += bb; f.z += bb; f.w += bb;
        *(float4*)&s->hT[0][j][ro] = f;
    }

    for (int t = 0; t < T_; t++) {
        const int cb = t & 1, nb = cb ^ 1;
        __syncthreads();   // (1) prev E-epi / h0 / Wt free

        // ---- A: inT = [phys_t ; cur] transposed ----
        for (int i = tid; i < BT * IN_K; i += NTHR) {
            int r = i / IN_K, k = i - r * IN_K;
            s->inT[k][r] = (k < P_) ? phys[((size_t)(b0 + r) * T_ + t) * P_ + k]
                                    : s->cur[r][k - P_];
        }
        // ---- B stage: W_in (180 x 72 -> stride B_WS) ----
        for (int i = tid; i < 180 * 18; i += NTHR) {
            int r = i / 18, c = i - r * 18;
            *(float4*)(s->Wt + r * B_WS + c * 4) = *(const float4*)(W_in + r * IN_K + c * 4);
        }
        __syncthreads();   // (2)

        // ---- B: xT = gelu(inT @ W_in^T + b_in) ----
        simple_phase<IN_K, B_WS, true>(s->Wt, s->bias + 1080,
                                       (const float (*)[BT])s->inT, s->xT, tid);
        __syncthreads();   // (3) xT ready, Wt free

        // ---- C: fused GRU. Thread j owns gate rows {j, j+180, j+360} of both
        //      W_ih and W_hh; 15 double-buffered KT=12 tiles. ----
        float air[4] = {0,0,0,0}, aiz[4] = {0,0,0,0}, ain[4] = {0,0,0,0};
        float ahr[4] = {0,0,0,0}, ahz[4] = {0,0,0,0}, ahn[4] = {0,0,0,0};
        stageC(s->Wt, W_ih, W_hh, 0, tid);
        __syncthreads();   // (4)
#pragma unroll 1
        for (int kt = 0; kt < C_NT; kt++) {
            if (kt + 1 < C_NT)
                stageC(s->Wt + ((kt + 1) & 1) * (1080 * C_WS), W_ih, W_hh,
                       (kt + 1) * C_KT, tid);
            if (on) {
                const float* wb = s->Wt + (kt & 1) * (1080 * C_WS);
                const float* xk = &s->xT[kt * C_KT][0];
                const float* hk = &s->hT[cb][kt * C_KT][0];
#pragma unroll
                for (int kb = 0; kb < C_KT; kb += 4) {
                    // x-half
                    {
                        float4 a0 = *(const float4*)(xk + (kb + 0) * BT + ro);
                        float4 a1 = *(const float4*)(xk + (kb + 1) * BT + ro);
                        float4 a2 = *(const float4*)(xk + (kb + 2) * BT + ro);
                        float4 a3 = *(const float4*)(xk + (kb + 3) * BT + ro);
                        float4 wr = *(const float4*)(wb + (j        ) * C_WS + kb);
                        float4 wz = *(const float4*)(wb + (j +  180 ) * C_WS + kb);
                        float4 wn = *(const float4*)(wb + (j +  360 ) * C_WS + kb);
                        fma16(air, a0, a1, a2, a3, wr);
                        fma16(aiz, a0, a1, a2, a3, wz);
                        fma16(ain, a0, a1, a2, a3, wn);
                    }
                    // h-half
                    {
                        float4 a0 = *(const float4*)(hk + (kb + 0) * BT + ro);
                        float4 a1 = *(const float4*)(hk + (kb + 1) * BT + ro);
                        float4 a2 = *(const float4*)(hk + (kb + 2) * BT + ro);
                        float4 a3 = *(const float4*)(hk + (kb + 3) * BT + ro);
                        float4 wr = *(const float4*)(wb + (j +  540 ) * C_WS + kb);
                        float4 wz = *(const float4*)(wb + (j +  720 ) * C_WS + kb);
                        float4 wn = *(const float4*)(wb + (j +  900 ) * C_WS + kb);
                        fma16(ahr, a0, a1, a2, a3, wr);
                        fma16(ahz, a0, a1, a2, a3, wz);
                        fma16(ahn, a0, a1, a2, a3, wn);
                    }
                }
            }
            __syncthreads();   // (5..19)
        }
        // C epilogue: gates in registers -> h_new
        if (on) {
            float bir = s->bias[j],        biz = s->bias[j + 180], bin_ = s->bias[j + 360];
            float bhr = s->bias[540 + j],  bhz = s->bias[720 + j], bhn  = s->bias[900 + j];
            float ho[4]; *(float4*)ho = *(const float4*)&s->hT[cb][j][ro];
            float hn[4];
#pragma unroll
            for (int rr = 0; rr < 4; rr++) {
                float rg = sigmoid_f(air[rr] + bir + ahr[rr] + bhr);
                float zg = sigmoid_f(aiz[rr] + biz + ahz[rr] + bhz);
                float ng = tanhf(ain[rr] + bin_ + rg * (ahn[rr] + bhn));
                hn[rr] = (1.f - zg) * ng + zg * ho[rr];
            }
            *(float4*)&s->hT[nb][j][ro] = *(float4*)hn;
        }

        // ---- D: oT = gelu([h_new ; cur] @ W_o1^T + b_o1), 4 tiles ----
        // tiles: k in W_o1 cols {0,64,128,180}, lens {64,64,52,64};
        // act: tiles 0-2 from hT[nb], tile 3 from curT.
        {
            const int lens[4] = {64, 64, 52, 64};
            const int offs[4] = {0, 64, 128, 180};
            float dacc[4] = {0,0,0,0};
            // stage tile 0
            for (int i = tid; i < 180 * 16; i += NTHR) {
                int r = i >> 4, c = i & 15;
                *(float4*)(s->Wt + r * D_WS + c * 4) =
                    *(const float4*)(W_o1 + r * 244 + c * 4);
            }
            __syncthreads();   // (20) also orders C-epi hT writes -> D compute
#pragma unroll
            for (int dt = 0; dt < 4; dt++) {
                if (dt < 3) {
                    float* db = s->Wt + ((dt + 1) & 1) * (180 * D_WS);
                    const int f4n = lens[dt + 1] >> 2;
                    for (int i = tid; i < 180 * 16; i += NTHR) {
                        int r = i >> 4, c = i & 15;
                        if (c < f4n)
                            *(float4*)(db + r * D_WS + c * 4) =
                                *(const float4*)(W_o1 + r * 244 + offs[dt + 1] + c * 4);
                    }
                }
                if (on) {
                    const float* wp = s->Wt + (dt & 1) * (180 * D_WS) + j * D_WS;
                    const float (*act)[BT] = (dt < 3) ? (const float (*)[BT])s->hT[nb]
                                                      : (const float (*)[BT])s->curT;
                    const int ab = (dt < 3) ? dt * 64 : 0;
#pragma unroll
                    for (int kb = 0; kb < lens[dt]; kb += 4) {
                        float4 w4 = *(const float4*)(wp + kb);
                        float4 a0 = *(const float4*)&act[ab + kb + 0][ro];
                        float4 a1 = *(const float4*)&act[ab + kb + 1][ro];
                        float4 a2 = *(const float4*)&act[ab + kb + 2][ro];
                        float4 a3 = *(const float4*)&act[ab + kb + 3][ro];
                        fma16(dacc, a0, a1, a2, a3, w4);
                    }
                }
                __syncthreads();   // (21..24)
            }
            if (on) {
                float bb = s->bias[1260 + j];
                float4 f;
                f.x = gelu_f(dacc[0] + bb); f.y = gelu_f(dacc[1] + bb);
                f.z = gelu_f(dacc[2] + bb); f.w = gelu_f(dacc[3] + bb);
                *(float4*)&s->oT[j][ro] = f;
            }
        }
        __syncthreads();   // (25) oT ready

        // ---- E: delta = oT @ W_o2^T + b_o2; cur = clip(cur + delta); store ----
        if (tid < 512) {
            const int ej = tid >> 3, g = tid & 7, r2 = g * 2;
            float a0 = 0.f, a1 = 0.f;
            const float* wp = s->WE + ej * E_WS;
#pragma unroll 5
            for (int k = 0; k < H_; k += 4) {
                float4 w4 = *(const float4*)(wp + k);
                float2 o0 = *(const float2*)&s->oT[k + 0][r2];
                float2 o1 = *(const float2*)&s->oT[k + 1][r2];
                float2 o2 = *(const float2*)&s->oT[k + 2][r2];
                float2 o3 = *(const float2*)&s->oT[k + 3][r2];
                a0 = fmaf(o0.x, w4.x, a0); a0 = fmaf(o1.x, w4.y, a0);
                a0 = fmaf(o2.x, w4.z, a0); a0 = fmaf(o3.x, w4.w, a0);
                a1 = fmaf(o0.y, w4.x, a1); a1 = fmaf(o1.y, w4.y, a1);
                a1 = fmaf(o2.y, w4.z, a1); a1 = fmaf(o3.y, w4.w, a1);
            }
            float bb = s->bias[1440 + ej];
            float c0 = fminf(fmaxf(s->cur[r2][ej]     + a0 + bb, 0.f), 1.f);
            float c1 = fminf(fmaxf(s->cur[r2 + 1][ej] + a1 + bb, 0.f), 1.f);
            s->cur[r2][ej] = c0;      s->cur[r2 + 1][ej] = c1;
            s->curT[ej][r2] = c0;     s->curT[ej][r2 + 1] = c1;
            out[((size_t)(b0 + r2)     * T_ + t) * L_ + ej] = c0;
            out[((size_t)(b0 + r2 + 1) * T_ + t) * L_ + ej] = c1;
        }
    }
}

extern "C" void kernel_launch(void* const* d_in, const int* in_sizes, int n_in,
                              void* d_out, int out_size)
{
    const float* phys    = (const float*)d_in[0];
    const float* latents = (const float*)d_in[1];
    const float* W_in    = (const float*)d_in[2];
    const float* b_in    = (const float*)d_in[3];
    const float* W_hp    = (const float*)d_in[4];
    const float* b_hp    = (const float*)d_in[5];
    const float* W_ih    = (const float*)d_in[6];
    const float* b_ih    = (const float*)d_in[7];
    const float* W_hh    = (const float*)d_in[8];
    const float* b_hh    = (const float*)d_in[9];
    const float* W_o1    = (const float*)d_in[10];
    const float* b_o1    = (const float*)d_in[11];
    const float* W_o2    = (const float*)d_in[12];
    const float* b_o2    = (const float*)d_in[13];
    float* out = (float*)d_out;

    static bool attr_set = false;
    if (!attr_set) {
        cudaFuncSetAttribute(latent_rnn_kernel,
                             cudaFuncAttributeMaxDynamicSharedMemorySize,
                             (int)sizeof(Smem));
        attr_set = true;
    }

    latent_rnn_kernel<<<B_ / BT, NTHR, sizeof(Smem)>>>(
        phys, latents, W_in, b_in, W_hp, b_hp, W_ih, b_ih, W_hh, b_hh,
        W_o1, b_o1, W_o2, b_o2, out);
}

// round 6
// speedup vs baseline: 1.5451x; 1.5451x over previous
#include <cuda_runtime.h>
#include <math.h>

// LatentRNN: B=2048, T=512, P=8, L=64, H=180
// 128 persistent CTAs x 16 batch rows, 640 threads.
// Prep kernel packs all weights transposed as [kq][col]{4 floats} so the
// main kernel's weight reads are fully coalesced LDG.128 (L2-resident),
// act reads are warp-uniform LDS. No per-step staging.

#define B_    2048
#define T_    512
#define P_    8
#define L_    64
#define H_    180
#define IN_K  72
#define BT    16
#define NTHR  640
#define GST   20          // padded row stride for giT/ghT (conflict-free stores)

// packed weights: [kq][ncols] float4
__device__ float4 g_Wc4[45 * 1080];   // fused [W_ih ; W_hh], K=180
__device__ float4 g_Wb4[18 * 180];    // W_in, K=72
__device__ float4 g_Wd4[61 * 180];    // W_o1, K=244
__device__ float4 g_We4[45 * 64];     // W_o2, K=180
__device__ float4 g_Wh4[16 * 180];    // W_hp, K=64

#define N_C (45 * 1080)
#define N_B (18 * 180)
#define N_D (61 * 180)
#define N_E (45 * 64)
#define N_H (16 * 180)

__global__ void prep_kernel(const float* __restrict__ Wih,
                            const float* __restrict__ Whh,
                            const float* __restrict__ Win,
                            const float* __restrict__ Wo1,
                            const float* __restrict__ Wo2,
                            const float* __restrict__ Whp)
{
    int i = blockIdx.x * blockDim.x + threadIdx.x;
    if (i < N_C) {
        int kq = i / 1080, g = i - kq * 1080;
        const float* src = (g < 540) ? (Wih + g * H_ + kq * 4)
                                     : (Whh + (g - 540) * H_ + kq * 4);
        g_Wc4[kq * 1080 + g] = *(const float4*)src;
        return;
    }
    i -= N_C;
    if (i < N_B) {
        int kq = i / 180, j = i - kq * 180;
        g_Wb4[kq * 180 + j] = *(const float4*)(Win + j * IN_K + kq * 4);
        return;
    }
    i -= N_B;
    if (i < N_D) {
        int kq = i / 180, j = i - kq * 180;
        g_Wd4[kq * 180 + j] = *(const float4*)(Wo1 + j * 244 + kq * 4);
        return;
    }
    i -= N_D;
    if (i < N_E) {
        int kq = i / 64, j = i - kq * 64;
        g_We4[kq * 64 + j] = *(const float4*)(Wo2 + j * H_ + kq * 4);
        return;
    }
    i -= N_E;
    if (i < N_H) {
        int kq = i / 180, j = i - kq * 180;
        g_Wh4[kq * 180 + j] = *(const float4*)(Whp + j * L_ + kq * 4);
    }
}

struct __align__(16) Smem {
    float inT[IN_K][BT];       // [phys_t ; cur] transposed (latentsT at init)
    float xT [H_][BT];         // gelu(in @ W_in^T)
    float hT [2][H_][BT];      // hidden state, double buffered
    float oT [H_][BT];         // gelu(cat @ W_o1^T)
    float giT[540][GST];       // gi (+bias); rows 0..179 become h_new, 180..243 cur
    float ghT[540][GST];       // gh (+bias)
    float cur[BT][L_];         // current latents (row-major)
    float sb [1684];           // biases: ih 0 | hh 540 | in 1080 | o1 1260 | o2 1440 | hp 1504
};

__device__ __forceinline__ float gelu_f(float v) {
    return 0.5f * v * (1.0f + erff(v * 0.70710678118654752440f));
}
__device__ __forceinline__ float sigmoid_f(float v) {
    return 1.0f / (1.0f + expf(-v));
}

// Column GEMM over packed weights: NR rows (from act base, stride LDA),
// K = 4*NKQ. Weight float4 per kq at w[kq*STRIDE] (coalesced across warp).
template<int NR, int NKQ, int STRIDE, int LDA>
__device__ __forceinline__ void pcol(const float4* __restrict__ w,
                                     const float* __restrict__ act,
                                     float* __restrict__ acc)
{
#pragma unroll 3
    for (int kq = 0; kq < NKQ; kq++) {
        float4 w4 = w[kq * STRIDE];
        const float* b = act + kq * 4 * LDA;
        float wk[4] = {w4.x, w4.y, w4.z, w4.w};
#pragma unroll
        for (int kk = 0; kk < 4; kk++) {
#pragma unroll
            for (int rq = 0; rq < NR / 4; rq++) {
                float4 a = *(const float4*)(b + kk * LDA + rq * 4);
                acc[rq*4+0] = fmaf(a.x, wk[kk], acc[rq*4+0]);
                acc[rq*4+1] = fmaf(a.y, wk[kk], acc[rq*4+1]);
                acc[rq*4+2] = fmaf(a.z, wk[kk], acc[rq*4+2]);
                acc[rq*4+3] = fmaf(a.w, wk[kk], acc[rq*4+3]);
            }
        }
    }
}

__global__ __launch_bounds__(NTHR, 1)
void latent_rnn_kernel(const float* __restrict__ phys,
                       const float* __restrict__ latents,
                       const float* __restrict__ b_in,
                       const float* __restrict__ b_hp,
                       const float* __restrict__ b_ih,
                       const float* __restrict__ b_hh,
                       const float* __restrict__ b_o1,
                       const float* __restrict__ b_o2,
                       float* __restrict__ out)
{
    extern __shared__ char smem_raw[];
    Smem* s = reinterpret_cast<Smem*>(smem_raw);
    const int tid = threadIdx.x;
    const int b0  = blockIdx.x * BT;

    // ---- init: cur = latents; latentsT into inT; biases into smem ----
    for (int i = tid; i < BT * L_; i += NTHR) {
        int r = i >> 6, l = i & 63;
        float v = latents[(b0 + r) * L_ + l];
        s->cur[r][l] = v;
        s->inT[l][r] = v;
    }
    for (int i = tid; i < 540;  i += NTHR) s->sb[i]        = b_ih[i];
    for (int i = tid; i < 540;  i += NTHR) s->sb[540 + i]  = b_hh[i];
    for (int i = tid; i < 180;  i += NTHR) s->sb[1080 + i] = b_in[i];
    for (int i = tid; i < 180;  i += NTHR) s->sb[1260 + i] = b_o1[i];
    for (int i = tid; i < 64;   i += NTHR) s->sb[1440 + i] = b_o2[i];
    for (int i = tid; i < 180;  i += NTHR) s->sb[1504 + i] = b_hp[i];
    __syncthreads();

    // ---- h0 = latents @ W_hp^T + b_hp ----
    if (tid < 360) {
        int j = tid >> 1, ro = (tid & 1) * 8;
        float acc[8] = {0,0,0,0,0,0,0,0};
        pcol<8, 16, 180, BT>(g_Wh4 + j, &s->inT[0][ro], acc);
        float bb = s->sb[1504 + j];
#pragma unroll
        for (int i = 0; i < 8; i++) s->hT[0][j][ro + i] = acc[i] + bb;
    }

    for (int t = 0; t < T_; t++) {
        const int cb = t & 1, nb = cb ^ 1;
        __syncthreads();   // (0) prev-E cur / h0 ready

        // ---- A: inT = [phys_t ; cur] transposed ----
        for (int i = tid; i < BT * IN_K; i += NTHR) {
            int r = i / IN_K, k = i - r * IN_K;
            s->inT[k][r] = (k < P_) ? phys[((size_t)(b0 + r) * T_ + t) * P_ + k]
                                    : s->cur[r][k - P_];
        }
        __syncthreads();   // (1) inT ready

        // ---- B: xT = gelu(inT @ W_in^T + b_in) ----
        if (tid < 360) {
            int j = tid >> 1, ro = (tid & 1) * 8;
            float acc[8] = {0,0,0,0,0,0,0,0};
            pcol<8, 18, 180, BT>(g_Wb4 + j, &s->inT[0][ro], acc);
            float bb = s->sb[1080 + j];
#pragma unroll
            for (int i = 0; i < 8; i++) s->xT[j][ro + i] = gelu_f(acc[i] + bb);
        }
        __syncthreads();   // (2) xT ready

        // ---- C: gi/gh = [x|h] @ [W_ih|W_hh]^T + bias (1080 cols, 2 passes) ----
        {
            int g = tid;     // pass 1
            {
                const float* act = (g < 540) ? &s->xT[0][0] : &s->hT[cb][0][0];
                float acc[16];
#pragma unroll
                for (int i = 0; i < 16; i++) acc[i] = 0.f;
                pcol<16, 45, 1080, BT>(g_Wc4 + g, act, acc);
                float bb = s->sb[g];    // ih for g<540, hh for g>=540 (contiguous)
                float* dst = (g < 540) ? s->giT[g] : s->ghT[g - 540];
#pragma unroll
                for (int rq = 0; rq < 4; rq++) {
                    float4 f;
                    f.x = acc[rq*4+0] + bb; f.y = acc[rq*4+1] + bb;
                    f.z = acc[rq*4+2] + bb; f.w = acc[rq*4+3] + bb;
                    *(float4*)(dst + rq * 4) = f;
                }
            }
            if (tid < 440) {  // pass 2: g = tid + 640 (all >= 540 -> gh)
                int g2 = tid + NTHR;
                float acc[16];
#pragma unroll
                for (int i = 0; i < 16; i++) acc[i] = 0.f;
                pcol<16, 45, 1080, BT>(g_Wc4 + g2, &s->hT[cb][0][0], acc);
                float bb = s->sb[g2];
                float* dst = s->ghT[g2 - 540];
#pragma unroll
                for (int rq = 0; rq < 4; rq++) {
                    float4 f;
                    f.x = acc[rq*4+0] + bb; f.y = acc[rq*4+1] + bb;
                    f.z = acc[rq*4+2] + bb; f.w = acc[rq*4+3] + bb;
                    *(float4*)(dst + rq * 4) = f;
                }
            }
        }
        __syncthreads();   // (3) gi/gh ready

        // ---- gates: h_new -> hT[nb]; giT[0..179] := h_new ----
        for (int i = tid; i < H_ * BT; i += NTHR) {
            int j = i >> 4, r = i & 15;
            float rg = sigmoid_f(s->giT[j][r]          + s->ghT[j][r]);
            float zg = sigmoid_f(s->giT[j + H_][r]     + s->ghT[j + H_][r]);
            float ng = tanhf    (s->giT[j + 2*H_][r]   + rg * s->ghT[j + 2*H_][r]);
            float hn = (1.f - zg) * ng + zg * s->hT[cb][j][r];
            s->hT[nb][j][r] = hn;
            s->giT[j][r] = hn;      // element owned by this thread (read first)
        }
        __syncthreads();   // (4) all gate reads done

        // ---- catT rows 180..243 = cur (transposed) ----
        for (int i = tid; i < L_ * BT; i += NTHR) {
            int l = i >> 4, r = i & 15;
            s->giT[H_ + l][r] = s->cur[r][l];
        }
        __syncthreads();   // (5) cat ready

        // ---- D: oT = gelu([h_new ; cur] @ W_o1^T + b_o1) ----
        if (tid < 360) {
            int j = tid >> 1, ro = (tid & 1) * 8;
            float acc[8] = {0,0,0,0,0,0,0,0};
            pcol<8, 61, 180, GST>(g_Wd4 + j, &s->giT[0][ro], acc);
            float bb = s->sb[1260 + j];
#pragma unroll
            for (int i = 0; i < 8; i++) s->oT[j][ro + i] = gelu_f(acc[i] + bb);
        }
        __syncthreads();   // (6) oT ready

        // ---- E: delta = oT @ W_o2^T + b_o2; cur = clip(cur + delta); store ----
        if (tid < 256) {
            int j = tid >> 2, ro = (tid & 3) * 4;
            float acc[4] = {0,0,0,0};
            pcol<4, 45, 64, BT>(g_We4 + j, &s->oT[0][ro], acc);
            float bb = s->sb[1440 + j];
#pragma unroll
            for (int i = 0; i < 4; i++) {
                int r = ro + i;
                float c = fminf(fmaxf(s->cur[r][j] + acc[i] + bb, 0.f), 1.f);
                s->cur[r][j] = c;
                out[((size_t)(b0 + r) * T_ + t) * L_ + j] = c;
            }
        }
    }
}

extern "C" void kernel_launch(void* const* d_in, const int* in_sizes, int n_in,
                              void* d_out, int out_size)
{
    const float* phys    = (const float*)d_in[0];
    const float* latents = (const float*)d_in[1];
    const float* W_in    = (const float*)d_in[2];
    const float* b_in    = (const float*)d_in[3];
    const float* W_hp    = (const float*)d_in[4];
    const float* b_hp    = (const float*)d_in[5];
    const float* W_ih    = (const float*)d_in[6];
    const float* b_ih    = (const float*)d_in[7];
    const float* W_hh    = (const float*)d_in[8];
    const float* b_hh    = (const float*)d_in[9];
    const float* W_o1    = (const float*)d_in[10];
    const float* b_o1    = (const float*)d_in[11];
    const float* W_o2    = (const float*)d_in[12];
    const float* b_o2    = (const float*)d_in[13];
    float* out = (float*)d_out;

    static bool attr_set = false;
    if (!attr_set) {
        cudaFuncSetAttribute(latent_rnn_kernel,
                             cudaFuncAttributeMaxDynamicSharedMemorySize,
                             (int)sizeof(Smem));
        attr_set = true;
    }

    prep_kernel<<<(N_C + N_B + N_D + N_E + N_H + 255) / 256, 256>>>(
        W_ih, W_hh, W_in, W_o1, W_o2, W_hp);

    latent_rnn_kernel<<<B_ / BT, NTHR, sizeof(Smem)>>>(
        phys, latents, b_in, b_hp, b_ih, b_hh, b_o1, b_o2, out);
}